// round 15
// baseline (speedup 1.0000x reference)
#include <cuda_runtime.h>
#include <cuda_bf16.h>
#include <mma.h>
#include <math.h>

using namespace nvcuda;

// ---------------------------------------------------------------------------
// TransformerCell: out = LN(relu(MHA(q=h, kv=concat(c,h,e,s), 8 heads)))
// Factorized exact algebra; ALL heavy math on HMMA (wmma bf16) with hi/lo
// split 3-product accumulation (~1e-5 rel err):
//   qp   = (h @ Wq^T + bq) / 8                  [N,512]   split bf16
//   qt_h = qp_h @ WkT_h^T                       [N,8,512] split bf16
//   attn: scores=qt.ctx (HMMA), softmax fp32, w=attn.ctx (HMMA), split bf16
//   o_h  = w_h @ Wv_h^T + bv_h                  [N,512]   split bf16
//   y    = o @ Wo^T + bo                        [N,512]   fp32
//   out = LN(relu(y))
// ---------------------------------------------------------------------------

#define NB    8192
#define DIM   512
#define HEADS 8
#define KCTX  35

typedef unsigned long long u64;
typedef unsigned int       u32;

// ---------------- scratch (device globals; no runtime allocation) ----------
__device__ __align__(16) __nv_bfloat16 g_h_hi [NB * DIM];
__device__ __align__(16) __nv_bfloat16 g_h_lo [NB * DIM];
__device__ __align__(16) __nv_bfloat16 g_wq_hi[DIM * DIM];
__device__ __align__(16) __nv_bfloat16 g_wq_lo[DIM * DIM];
__device__ __align__(16) __nv_bfloat16 g_wkT_hi[DIM * DIM];   // [h][512][64] K-major
__device__ __align__(16) __nv_bfloat16 g_wkT_lo[DIM * DIM];
__device__ __align__(16) __nv_bfloat16 g_wv_hi[DIM * DIM];
__device__ __align__(16) __nv_bfloat16 g_wv_lo[DIM * DIM];
__device__ __align__(16) __nv_bfloat16 g_wo_hi[DIM * DIM];
__device__ __align__(16) __nv_bfloat16 g_wo_lo[DIM * DIM];
__device__ __align__(16) __nv_bfloat16 g_qp_hi[NB * DIM];
__device__ __align__(16) __nv_bfloat16 g_qp_lo[NB * DIM];
__device__ __align__(16) __nv_bfloat16 g_qt_hi[NB * HEADS * DIM];  // 64 MB
__device__ __align__(16) __nv_bfloat16 g_qt_lo[NB * HEADS * DIM];  // 64 MB
__device__ __align__(16) __nv_bfloat16 g_w_hi[NB * HEADS * DIM];   // 64 MB
__device__ __align__(16) __nv_bfloat16 g_w_lo[NB * HEADS * DIM];   // 64 MB
__device__ __align__(16) __nv_bfloat16 g_o_hi[NB * DIM];
__device__ __align__(16) __nv_bfloat16 g_o_lo[NB * DIM];
__device__ __align__(16) float         g_y   [NB * DIM];

// split fp32 -> bf16 hi + bf16 lo (lo = rn(residual))
__device__ __forceinline__ void split1(float v, __nv_bfloat16& hi, __nv_bfloat16& lo) {
    hi = __float2bfloat16(v);
    lo = __float2bfloat16(v - __bfloat162float(hi));
}
__device__ __forceinline__ void split_store4(__nv_bfloat16* hp, __nv_bfloat16* lp, float4 f) {
    union { __nv_bfloat16 b[4]; uint2 u; } H, L;
    split1(f.x, H.b[0], L.b[0]);
    split1(f.y, H.b[1], L.b[1]);
    split1(f.z, H.b[2], L.b[2]);
    split1(f.w, H.b[3], L.b[3]);
    *(uint2*)hp = H.u;
    *(uint2*)lp = L.u;
}

__device__ __forceinline__ u32 smem_u32(const void* p) {
    u32 a;
    asm("{ .reg .u64 t; cvta.to.shared.u64 t, %1; cvt.u32.u64 %0, t; }"
        : "=r"(a) : "l"(p));
    return a;
}
__device__ __forceinline__ void cpasync16(u32 dst, const void* src) {
    asm volatile("cp.async.cg.shared.global [%0], [%1], 16;"
                 :: "r"(dst), "l"(src) : "memory");
}
#define CP_COMMIT() asm volatile("cp.async.commit_group;" ::: "memory")

// ---------------------------------------------------------------------------
// split conversion kernels
// ---------------------------------------------------------------------------
__global__ void __launch_bounds__(256)
splitF32(const float* __restrict__ x, __nv_bfloat16* __restrict__ hi,
         __nv_bfloat16* __restrict__ lo)
{
    const int i = blockIdx.x * 256 + threadIdx.x;   // float4 index
    float4 v = ((const float4*)x)[i];
    split_store4(hi + 4 * (long)i, lo + 4 * (long)i, v);
}

// WkT[h][n][k] = split(Wk[h*64+k][n]); flat t = h*32768 + n*64 + k
__global__ void __launch_bounds__(256)
splitWkT(const float* __restrict__ Wk, __nv_bfloat16* __restrict__ hi,
         __nv_bfloat16* __restrict__ lo)
{
    const int t = blockIdx.x * 256 + threadIdx.x;
    const int k = t & 63, n = (t >> 6) & 511, h = t >> 15;
    float v = Wk[(h * 64 + k) * DIM + n];
    __nv_bfloat16 a, b;
    split1(v, a, b);
    hi[t] = a; lo[t] = b;
}

// ---------------------------------------------------------------------------
// wmma bf16 GEMM, hi/lo split (3 products), cp.async double buffer.
//   C[m, z*cz + bn + j] = (sum_k A[m,k]*B[n,k] + bias) * alpha
// Block: 256 thr = 8 warps (4m x 2n); tile M=128, N=BN, BK=32.
// ---------------------------------------------------------------------------
template <int BN, bool SPLIT_OUT>
__global__ void __launch_bounds__(256)
wmmaGemm(const __nv_bfloat16* __restrict__ aHi, const __nv_bfloat16* __restrict__ aLo,
         int lda, int az,
         const __nv_bfloat16* __restrict__ bHi, const __nv_bfloat16* __restrict__ bLo,
         int ldb, int bz,
         const float* __restrict__ bias, int biasz,
         float* __restrict__ cF,
         __nv_bfloat16* __restrict__ cHi, __nv_bfloat16* __restrict__ cLo,
         int ldc, long cz,
         int K, float alpha)
{
    extern __shared__ __align__(16) char smem[];
    constexpr int A_SZ  = 128 * 40 * 2;               // bytes, one matrix
    constexpr int B_SZ  = BN * 40 * 2;
    constexpr int STAGE = 2 * A_SZ + 2 * B_SZ;
    constexpr int OFF_BIAS = 0;
    constexpr int OFF_T    = 1024;
    constexpr int WN    = BN / 2;
    constexpr int NFRAG = WN / 16;

    const u32 sb  = smem_u32(smem);
    const int tid = threadIdx.x;
    const int wid = tid >> 5;
    const int bm  = blockIdx.y * 128;
    const int bn  = blockIdx.x * BN;
    const int z   = blockIdx.z;
    const int wm  = (wid >> 1) * 32;
    const int wn  = (wid & 1) * WN;

    aHi += (long)z * az;  aLo += (long)z * az;
    bHi += (long)z * bz;  bLo += (long)z * bz;

    if (tid < BN) {
        float bvv = bias ? bias[(long)z * biasz + bn + tid] : 0.f;
        *(float*)(smem + OFF_BIAS + tid * 4) = bvv;
    }

#define LOAD_CHUNK(st, kOff)                                                   \
    {                                                                          \
        const u32 aHiS = sb + OFF_T + (st) * STAGE;                            \
        const u32 aLoS = aHiS + A_SZ;                                          \
        const u32 bHiS = aLoS + A_SZ;                                          \
        const u32 bLoS = bHiS + B_SZ;                                          \
        _Pragma("unroll")                                                      \
        for (int i = 0; i < 2; i++) {                                          \
            int t = tid + 256 * i;                                             \
            int r = t >> 2, cq = t & 3;                                        \
            const long go = (long)(bm + r) * lda + (kOff) + cq * 8;            \
            cpasync16(aHiS + r * 80 + cq * 16, aHi + go);                      \
            cpasync16(aLoS + r * 80 + cq * 16, aLo + go);                      \
        }                                                                      \
        _Pragma("unroll")                                                      \
        for (int i = 0; i < BN / 64; i++) {                                    \
            int t = tid + 256 * i;                                             \
            int r = t >> 2, cq = t & 3;                                        \
            const long go = (long)(bn + r) * ldb + (kOff) + cq * 8;            \
            cpasync16(bHiS + r * 80 + cq * 16, bHi + go);                      \
            cpasync16(bLoS + r * 80 + cq * 16, bLo + go);                      \
        }                                                                      \
    }

    wmma::fragment<wmma::accumulator, 16, 16, 16, float> acc[2][NFRAG];
#pragma unroll
    for (int mi = 0; mi < 2; mi++)
#pragma unroll
        for (int ni = 0; ni < NFRAG; ni++) wmma::fill_fragment(acc[mi][ni], 0.f);

    const int nChunks = K >> 5;                       // BK = 32
    LOAD_CHUNK(0, 0);
    CP_COMMIT();

    for (int kc = 0; kc < nChunks; kc++) {
        const int cur = kc & 1;
        if (kc + 1 < nChunks) {
            LOAD_CHUNK(!cur, (kc + 1) * 32);
            CP_COMMIT();
            asm volatile("cp.async.wait_group 1;" ::: "memory");
        } else {
            asm volatile("cp.async.wait_group 0;" ::: "memory");
        }
        __syncthreads();

        __nv_bfloat16* AsHi = (__nv_bfloat16*)(smem + OFF_T + cur * STAGE);
        __nv_bfloat16* AsLo = AsHi + 128 * 40;
        __nv_bfloat16* BsHi = AsLo + 128 * 40;
        __nv_bfloat16* BsLo = BsHi + BN * 40;

#pragma unroll
        for (int kf = 0; kf < 32; kf += 16) {
            wmma::fragment<wmma::matrix_a, 16, 16, 16, __nv_bfloat16, wmma::row_major> aH[2], aL[2];
#pragma unroll
            for (int mi = 0; mi < 2; mi++) {
                wmma::load_matrix_sync(aH[mi], AsHi + (wm + mi * 16) * 40 + kf, 40);
                wmma::load_matrix_sync(aL[mi], AsLo + (wm + mi * 16) * 40 + kf, 40);
            }
#pragma unroll
            for (int ni = 0; ni < NFRAG; ni++) {
                wmma::fragment<wmma::matrix_b, 16, 16, 16, __nv_bfloat16, wmma::col_major> bH, bL;
                wmma::load_matrix_sync(bH, BsHi + (wn + ni * 16) * 40 + kf, 40);
                wmma::load_matrix_sync(bL, BsLo + (wn + ni * 16) * 40 + kf, 40);
#pragma unroll
                for (int mi = 0; mi < 2; mi++) {
                    wmma::mma_sync(acc[mi][ni], aH[mi], bH, acc[mi][ni]);
                    wmma::mma_sync(acc[mi][ni], aH[mi], bL, acc[mi][ni]);
                    wmma::mma_sync(acc[mi][ni], aL[mi], bH, acc[mi][ni]);
                }
            }
        }
        __syncthreads();
    }
#undef LOAD_CHUNK

    // ---- epilogue: frags -> smem C overlay -> bias/alpha/(split) global ----
    float* Cs = (float*)(smem + OFF_T);
#pragma unroll
    for (int mi = 0; mi < 2; mi++)
#pragma unroll
        for (int ni = 0; ni < NFRAG; ni++)
            wmma::store_matrix_sync(Cs + (wm + mi * 16) * BN + wn + ni * 16,
                                    acc[mi][ni], BN, wmma::mem_row_major);
    __syncthreads();

    const float* bs = (const float*)(smem + OFF_BIAS);
    constexpr int NV = 128 * BN / 4 / 256;
#pragma unroll
    for (int i = 0; i < NV; i++) {
        int t = tid + 256 * i;
        int r = t / (BN / 4);
        int c4 = t % (BN / 4);
        float4 v = *(float4*)(Cs + r * BN + c4 * 4);
        v.x = (v.x + bs[c4 * 4 + 0]) * alpha;
        v.y = (v.y + bs[c4 * 4 + 1]) * alpha;
        v.z = (v.z + bs[c4 * 4 + 2]) * alpha;
        v.w = (v.w + bs[c4 * 4 + 3]) * alpha;
        const long off = (long)(bm + r) * ldc + (long)z * cz + bn + c4 * 4;
        if (SPLIT_OUT) split_store4(cHi + off, cLo + off, v);
        else           *(float4*)(cF + off) = v;
    }
}

// ---------------------------------------------------------------------------
// HMMA attention core: one CTA per batch, 512 threads = 16 warps.
// scores = qt[16pad,512] . ctx[48pad,512]^T  (split bf16, 3 products)
// softmax fp32 (warp shuffle), attn split to bf16 hi/lo
// w = attn[16,48] @ ctx[48,512]              (split, 3 products)
// ctx staged fp32->split bf16 in smem; all pads zeroed (NaN-safe).
// ---------------------------------------------------------------------------
__global__ void __launch_bounds__(512)
attn_hmma(const __nv_bfloat16* __restrict__ qtHiG, const __nv_bfloat16* __restrict__ qtLoG,
          const float* __restrict__ cc, const float* __restrict__ hv,
          const float* __restrict__ ev, const float* __restrict__ sv,
          __nv_bfloat16* __restrict__ whi, __nv_bfloat16* __restrict__ wlo)
{
    extern __shared__ __align__(16) char sm[];
    constexpr int LDX = 520;                                  // bf16 elements
    __nv_bfloat16* ctxHi = (__nv_bfloat16*)sm;                // [48][520]
    __nv_bfloat16* ctxLo = ctxHi + 48 * LDX;                  // [48][520]
    __nv_bfloat16* qtHs  = ctxLo + 48 * LDX;                  // [16][520]
    __nv_bfloat16* qtLs  = qtHs + 16 * LDX;                   // [16][520]
    float*         sp    = (float*)(qtLs + 16 * LDX);         // [12][16][16]
    __nv_bfloat16* atHi  = (__nv_bfloat16*)(sp + 12 * 256);   // [16][48]
    __nv_bfloat16* atLo  = atHi + 16 * 48;                    // [16][48]

    const int n    = blockIdx.x;
    const int tid  = threadIdx.x;
    const int lane = tid & 31;
    const int warp = tid >> 5;

    // ---- stage qt (split bf16, rows 0-7) + zero pad rows 8-15 --------------
    {
        const int r = tid >> 6;              // 0..7
        const int c = (tid & 63) * 8;        // 0..504
        const long g = (long)n * (HEADS * DIM) + r * DIM + c;
        *(uint4*)(qtHs + r * LDX + c) = *(const uint4*)(qtHiG + g);
        *(uint4*)(qtLs + r * LDX + c) = *(const uint4*)(qtLoG + g);
        const uint4 z = make_uint4(0, 0, 0, 0);
        *(uint4*)(qtHs + (8 + r) * LDX + c) = z;
        *(uint4*)(qtLs + (8 + r) * LDX + c) = z;
    }
    // ---- stage ctx rows 0-34 (fp32 -> split bf16); zero rows 35-47 ---------
    for (int i = tid; i < 35 * 128; i += 512) {
        const int row = i >> 7;
        const int c4  = (i & 127) * 4;
        const float* src = (row < 32)
            ? cc + ((long)n * 32 + row) * DIM
            : ((row == 32) ? hv : (row == 33) ? ev : sv) + (long)n * DIM;
        float4 v = *(const float4*)(src + c4);
        split_store4(ctxHi + row * LDX + c4, ctxLo + row * LDX + c4, v);
    }
    {
        const uint4 z = make_uint4(0, 0, 0, 0);
        for (int i = tid; i < 13 * 64; i += 512) {
            const int row = 35 + (i >> 6);
            const int c = (i & 63) * 8;
            *(uint4*)(ctxHi + row * LDX + c) = z;
            *(uint4*)(ctxLo + row * LDX + c) = z;
        }
    }
    __syncthreads();

    // ---- phase B: score partials (12 warps = 3 n-frags x 4 k-quarters) ----
    if (warp < 12) {
        const int nf = warp >> 2;
        const int kq = warp & 3;
        wmma::fragment<wmma::accumulator, 16, 16, 16, float> acc;
        wmma::fill_fragment(acc, 0.f);
#pragma unroll
        for (int ks = 0; ks < 8; ks++) {
            const int k = kq * 128 + ks * 16;
            wmma::fragment<wmma::matrix_a, 16, 16, 16, __nv_bfloat16, wmma::row_major> aH, aL;
            wmma::fragment<wmma::matrix_b, 16, 16, 16, __nv_bfloat16, wmma::col_major> bH, bL;
            wmma::load_matrix_sync(aH, qtHs + k, LDX);
            wmma::load_matrix_sync(aL, qtLs + k, LDX);
            wmma::load_matrix_sync(bH, ctxHi + nf * 16 * LDX + k, LDX);
            wmma::load_matrix_sync(bL, ctxLo + nf * 16 * LDX + k, LDX);
            wmma::mma_sync(acc, aH, bH, acc);
            wmma::mma_sync(acc, aH, bL, acc);
            wmma::mma_sync(acc, aL, bH, acc);
        }
        wmma::store_matrix_sync(sp + warp * 256, acc, 16, wmma::mem_row_major);
    }
    __syncthreads();

    // ---- softmax (warps 0-7, warp = head) + attn split; zero pads ----------
    if (warp < 8) {
        const int hh = warp;
        const int b1 = ((lane >> 4) * 4) * 256 + hh * 16 + (lane & 15);
        float s1 = sp[b1] + sp[b1 + 256] + sp[b1 + 512] + sp[b1 + 768];
        float s2 = -3.0e38f;
        if (lane < 3) {
            const int j = 32 + lane;
            const int b2 = ((j >> 4) * 4) * 256 + hh * 16 + (j & 15);
            s2 = sp[b2] + sp[b2 + 256] + sp[b2 + 512] + sp[b2 + 768];
        }
        float m = fmaxf(s1, s2);
#pragma unroll
        for (int o = 16; o; o >>= 1)
            m = fmaxf(m, __shfl_xor_sync(0xffffffffu, m, o));
        float e1 = expf(s1 - m);
        float e2 = (lane < 3) ? expf(s2 - m) : 0.f;
        float sum = e1 + e2;
#pragma unroll
        for (int o = 16; o; o >>= 1)
            sum += __shfl_xor_sync(0xffffffffu, sum, o);
        const float inv = 1.f / sum;
        __nv_bfloat16 hi, lo;
        split1(e1 * inv, hi, lo);
        atHi[hh * 48 + lane] = hi;  atLo[hh * 48 + lane] = lo;
        if (lane < 3) {
            split1(e2 * inv, hi, lo);
            atHi[hh * 48 + 32 + lane] = hi;  atLo[hh * 48 + 32 + lane] = lo;
        }
        if (lane < 13) {
            atHi[hh * 48 + 35 + lane] = __float2bfloat16(0.f);
            atLo[hh * 48 + 35 + lane] = __float2bfloat16(0.f);
        }
    } else {
        const int t = tid - 256;                  // 0..255
        for (int i = t; i < 8 * 48; i += 256) {
            const int idx = (8 + i / 48) * 48 + (i % 48);
            atHi[idx] = __float2bfloat16(0.f);
            atLo[idx] = __float2bfloat16(0.f);
        }
    }
    __syncthreads();

    // ---- phase C: w = attn @ ctx (16 warps x 2 n-frags) --------------------
    wmma::fragment<wmma::accumulator, 16, 16, 16, float> acc2[2];
    {
        wmma::fragment<wmma::matrix_a, 16, 16, 16, __nv_bfloat16, wmma::row_major> cAH[3], cAL[3];
#pragma unroll
        for (int k3 = 0; k3 < 3; k3++) {
            wmma::load_matrix_sync(cAH[k3], atHi + k3 * 16, 48);
            wmma::load_matrix_sync(cAL[k3], atLo + k3 * 16, 48);
        }
#pragma unroll
        for (int f = 0; f < 2; f++) {
            const int col = (warp * 2 + f) * 16;
            wmma::fill_fragment(acc2[f], 0.f);
#pragma unroll
            for (int k3 = 0; k3 < 3; k3++) {
                wmma::fragment<wmma::matrix_b, 16, 16, 16, __nv_bfloat16, wmma::row_major> bH, bL;
                wmma::load_matrix_sync(bH, ctxHi + k3 * 16 * LDX + col, LDX);
                wmma::load_matrix_sync(bL, ctxLo + k3 * 16 * LDX + col, LDX);
                wmma::mma_sync(acc2[f], cAH[k3], bH, acc2[f]);
                wmma::mma_sync(acc2[f], cAL[k3], bH, acc2[f]);
                wmma::mma_sync(acc2[f], cAH[k3], bL, acc2[f]);
            }
        }
    }
    __syncthreads();                              // ctx reads done -> overlay ok

    float* ov = (float*)sm;                        // [16][520] fp32 overlay
#pragma unroll
    for (int f = 0; f < 2; f++)
        wmma::store_matrix_sync(ov + (warp * 2 + f) * 16, acc2[f], LDX,
                                wmma::mem_row_major);
    __syncthreads();

    // ---- writeout rows 0-7 (heads) with split ------------------------------
#pragma unroll
    for (int ii = 0; ii < 2; ii++) {
        const int i = tid + ii * 512;             // 0..1023
        const int row = i >> 7;                   // 0..7
        const int c4 = (i & 127) * 4;
        float4 v = *(const float4*)(ov + row * LDX + c4);
        const long g = (long)n * (HEADS * DIM) + row * DIM + c4;
        split_store4(whi + g, wlo + g, v);
    }
}

// ---------------------------------------------------------------------------
// relu + LayerNorm (ddof=1, eps added to STD). One warp per row.
// ---------------------------------------------------------------------------
__global__ void __launch_bounds__(256)
relu_ln(const float* __restrict__ y, const float* __restrict__ ln_a,
        const float* __restrict__ ln_b, float* __restrict__ out)
{
    const int lane = threadIdx.x & 31;
    const int warp = threadIdx.x >> 5;
    const int row  = blockIdx.x * 8 + warp;

    const float4* xr = (const float4*)(y + (long)row * DIM);
    float4 v[4];
    float sum = 0.f;
#pragma unroll
    for (int i = 0; i < 4; i++) {
        float4 x = xr[lane + 32 * i];
        x.x = fmaxf(x.x, 0.f); x.y = fmaxf(x.y, 0.f);
        x.z = fmaxf(x.z, 0.f); x.w = fmaxf(x.w, 0.f);
        v[i] = x;
        sum += x.x + x.y + x.z + x.w;
    }
#pragma unroll
    for (int o = 16; o; o >>= 1) sum += __shfl_xor_sync(0xffffffffu, sum, o);
    const float mean = sum * (1.f / (float)DIM);

    float ssq = 0.f;
#pragma unroll
    for (int i = 0; i < 4; i++) {
        float dx;
        dx = v[i].x - mean; ssq = fmaf(dx, dx, ssq);
        dx = v[i].y - mean; ssq = fmaf(dx, dx, ssq);
        dx = v[i].z - mean; ssq = fmaf(dx, dx, ssq);
        dx = v[i].w - mean; ssq = fmaf(dx, dx, ssq);
    }
#pragma unroll
    for (int o = 16; o; o >>= 1) ssq += __shfl_xor_sync(0xffffffffu, ssq, o);
    const float stddev = sqrtf(ssq * (1.f / (float)(DIM - 1)));
    const float inv = 1.f / (stddev + 1e-6f);

    float4* orow = (float4*)(out + (long)row * DIM);
    const float4* a4 = (const float4*)ln_a;
    const float4* b4 = (const float4*)ln_b;
#pragma unroll
    for (int i = 0; i < 4; i++) {
        const int idx = lane + 32 * i;
        float4 a = a4[idx], b = b4[idx], o4;
        o4.x = fmaf(a.x * inv, v[i].x - mean, b.x);
        o4.y = fmaf(a.y * inv, v[i].y - mean, b.y);
        o4.z = fmaf(a.z * inv, v[i].z - mean, b.z);
        o4.w = fmaf(a.w * inv, v[i].w - mean, b.w);
        orow[idx] = o4;
    }
}

// ---------------------------------------------------------------------------
extern "C" void kernel_launch(void* const* d_in, const int* in_sizes, int n_in,
                              void* d_out, int out_size)
{
    const float* c   = (const float*)d_in[0];
    const float* h   = (const float*)d_in[1];
    const float* e   = (const float*)d_in[2];
    const float* s   = (const float*)d_in[3];
    const float* Wq  = (const float*)d_in[4];
    const float* bq  = (const float*)d_in[5];
    const float* Wk  = (const float*)d_in[6];
    /* bk = d_in[7] unused: constant across softmax axis, drops exactly */
    const float* Wv  = (const float*)d_in[8];
    const float* bv  = (const float*)d_in[9];
    const float* Wo  = (const float*)d_in[10];
    const float* bo  = (const float*)d_in[11];
    const float* la  = (const float*)d_in[12];
    const float* lb  = (const float*)d_in[13];
    float* out = (float*)d_out;

    void *p;
    __nv_bfloat16 *hHi, *hLo, *wqHi, *wqLo, *wkHi, *wkLo, *wvHi, *wvLo, *woHi, *woLo;
    __nv_bfloat16 *qpHi, *qpLo, *qtHi, *qtLo, *wHi, *wLo, *oHi, *oLo;
    float *y;
    cudaGetSymbolAddress(&p, g_h_hi);   hHi  = (__nv_bfloat16*)p;
    cudaGetSymbolAddress(&p, g_h_lo);   hLo  = (__nv_bfloat16*)p;
    cudaGetSymbolAddress(&p, g_wq_hi);  wqHi = (__nv_bfloat16*)p;
    cudaGetSymbolAddress(&p, g_wq_lo);  wqLo = (__nv_bfloat16*)p;
    cudaGetSymbolAddress(&p, g_wkT_hi); wkHi = (__nv_bfloat16*)p;
    cudaGetSymbolAddress(&p, g_wkT_lo); wkLo = (__nv_bfloat16*)p;
    cudaGetSymbolAddress(&p, g_wv_hi);  wvHi = (__nv_bfloat16*)p;
    cudaGetSymbolAddress(&p, g_wv_lo);  wvLo = (__nv_bfloat16*)p;
    cudaGetSymbolAddress(&p, g_wo_hi);  woHi = (__nv_bfloat16*)p;
    cudaGetSymbolAddress(&p, g_wo_lo);  woLo = (__nv_bfloat16*)p;
    cudaGetSymbolAddress(&p, g_qp_hi);  qpHi = (__nv_bfloat16*)p;
    cudaGetSymbolAddress(&p, g_qp_lo);  qpLo = (__nv_bfloat16*)p;
    cudaGetSymbolAddress(&p, g_qt_hi);  qtHi = (__nv_bfloat16*)p;
    cudaGetSymbolAddress(&p, g_qt_lo);  qtLo = (__nv_bfloat16*)p;
    cudaGetSymbolAddress(&p, g_w_hi);   wHi  = (__nv_bfloat16*)p;
    cudaGetSymbolAddress(&p, g_w_lo);   wLo  = (__nv_bfloat16*)p;
    cudaGetSymbolAddress(&p, g_o_hi);   oHi  = (__nv_bfloat16*)p;
    cudaGetSymbolAddress(&p, g_o_lo);   oLo  = (__nv_bfloat16*)p;
    cudaGetSymbolAddress(&p, g_y);      y    = (float*)p;

    // smem sizes: 1024 + max(2 stages, C overlay)
    const int ST128 = 2 * (2 * 128 * 40 * 2 + 2 * 128 * 40 * 2);  // 81920
    const int ST64  = 2 * (2 * 128 * 40 * 2 + 2 * 64 * 40 * 2);   // 61440
    const int SM128 = 1024 + (ST128 > 128 * 128 * 4 ? ST128 : 128 * 128 * 4);
    const int SM64  = 1024 + (ST64  > 128 * 64 * 4  ? ST64  : 128 * 64 * 4);
    // attn smem: ctx split + qt split + partials + attn split
    const int ATTN_SMEM = 2 * (48 * 520) * 2 + 2 * (16 * 520) * 2 +
                          12 * 256 * 4 + 2 * (16 * 48) * 2;        // 148480

    cudaFuncSetAttribute(wmmaGemm<128, true>,
                         cudaFuncAttributeMaxDynamicSharedMemorySize, SM128);
    cudaFuncSetAttribute(wmmaGemm<128, false>,
                         cudaFuncAttributeMaxDynamicSharedMemorySize, SM128);
    cudaFuncSetAttribute(wmmaGemm<64, true>,
                         cudaFuncAttributeMaxDynamicSharedMemorySize, SM64);
    cudaFuncSetAttribute(attn_hmma,
                         cudaFuncAttributeMaxDynamicSharedMemorySize, ATTN_SMEM);

    // 0) conversions
    splitF32<<<NB * DIM / 4 / 256, 256>>>(h, hHi, hLo);
    splitF32<<<DIM * DIM / 4 / 256, 256>>>(Wq, wqHi, wqLo);
    splitF32<<<DIM * DIM / 4 / 256, 256>>>(Wv, wvHi, wvLo);
    splitF32<<<DIM * DIM / 4 / 256, 256>>>(Wo, woHi, woLo);
    splitWkT<<<DIM * DIM / 256, 256>>>(Wk, wkHi, wkLo);

    // 1) qp = (h @ Wq^T + bq)*0.125 -> split bf16
    wmmaGemm<128, true><<<dim3(4, 64, 1), 256, SM128>>>(
        hHi, hLo, DIM, 0, wqHi, wqLo, DIM, 0, bq, 0,
        (float*)0, qpHi, qpLo, DIM, 0, DIM, 0.125f);

    // 2) qt[n, h*512+d] = qp_h @ WkT_h^T  (z = head, K = 64) -> split bf16
    wmmaGemm<128, true><<<dim3(4, 64, 8), 256, SM128>>>(
        qpHi, qpLo, DIM, 64, wkHi, wkLo, 64, 512 * 64, (const float*)0, 0,
        (float*)0, qtHi, qtLo, HEADS * DIM, DIM, 64, 1.0f);

    // 3) HMMA attention core -> w split bf16
    attn_hmma<<<NB, 512, ATTN_SMEM>>>(qtHi, qtLo, c, h, e, s, wHi, wLo);

    // 4) o[:, h*64..] = w_h @ Wv_h^T + bv_h (z = head) -> split bf16
    wmmaGemm<64, true><<<dim3(1, 64, 8), 256, SM64>>>(
        wHi, wLo, HEADS * DIM, DIM, wvHi, wvLo, DIM, 64 * DIM, bv, 64,
        (float*)0, oHi, oLo, DIM, 64, DIM, 1.0f);

    // 5) y = o @ Wo^T + bo -> fp32
    wmmaGemm<128, false><<<dim3(4, 64, 1), 256, SM128>>>(
        oHi, oLo, DIM, 0, woHi, woLo, DIM, 0, bo, 0,
        y, (__nv_bfloat16*)0, (__nv_bfloat16*)0, DIM, 0, DIM, 1.0f);

    // 6) out = LN(relu(y))
    relu_ln<<<NB / 8, 256>>>(y, la, lb, out);
}

// round 16
// speedup vs baseline: 1.5813x; 1.5813x over previous
#include <cuda_runtime.h>
#include <cuda_bf16.h>
#include <mma.h>
#include <math.h>

using namespace nvcuda;

// ---------------------------------------------------------------------------
// TransformerCell: out = LN(relu(MHA(q=h, kv=concat(c,h,e,s), 8 heads)))
// Factorized exact algebra; GEMMs on wmma bf16 (HMMA) with hi/lo split
// (3-product MMA, ~1e-5 rel err). Attention core SIMT fp32 (f32x2), 4 heads
// per warp to halve smem-crossbar traffic; ctx staged via cp.async.
// ---------------------------------------------------------------------------

#define NB    8192
#define DIM   512
#define HEADS 8
#define KCTX  35

typedef unsigned long long u64;
typedef unsigned int       u32;

// ---------------- scratch (device globals; no runtime allocation) ----------
__device__ __align__(16) __nv_bfloat16 g_h_hi [NB * DIM];
__device__ __align__(16) __nv_bfloat16 g_h_lo [NB * DIM];
__device__ __align__(16) __nv_bfloat16 g_wq_hi[DIM * DIM];
__device__ __align__(16) __nv_bfloat16 g_wq_lo[DIM * DIM];
__device__ __align__(16) __nv_bfloat16 g_wkT_hi[DIM * DIM];   // [h][512][64] K-major
__device__ __align__(16) __nv_bfloat16 g_wkT_lo[DIM * DIM];
__device__ __align__(16) __nv_bfloat16 g_wv_hi[DIM * DIM];
__device__ __align__(16) __nv_bfloat16 g_wv_lo[DIM * DIM];
__device__ __align__(16) __nv_bfloat16 g_wo_hi[DIM * DIM];
__device__ __align__(16) __nv_bfloat16 g_wo_lo[DIM * DIM];
__device__ __align__(16) __nv_bfloat16 g_qp_hi[NB * DIM];
__device__ __align__(16) __nv_bfloat16 g_qp_lo[NB * DIM];
__device__ __align__(16) float         g_qt  [NB * HEADS * DIM];   // 128 MB
__device__ __align__(16) __nv_bfloat16 g_w_hi[NB * HEADS * DIM];   // 64 MB
__device__ __align__(16) __nv_bfloat16 g_w_lo[NB * HEADS * DIM];   // 64 MB
__device__ __align__(16) __nv_bfloat16 g_o_hi[NB * DIM];
__device__ __align__(16) __nv_bfloat16 g_o_lo[NB * DIM];
__device__ __align__(16) float         g_y   [NB * DIM];

// split fp32 -> bf16 hi + bf16 lo (lo = rn(residual))
__device__ __forceinline__ void split1(float v, __nv_bfloat16& hi, __nv_bfloat16& lo) {
    hi = __float2bfloat16(v);
    lo = __float2bfloat16(v - __bfloat162float(hi));
}
__device__ __forceinline__ void split_store4(__nv_bfloat16* hp, __nv_bfloat16* lp, float4 f) {
    union { __nv_bfloat16 b[4]; uint2 u; } H, L;
    split1(f.x, H.b[0], L.b[0]);
    split1(f.y, H.b[1], L.b[1]);
    split1(f.z, H.b[2], L.b[2]);
    split1(f.w, H.b[3], L.b[3]);
    *(uint2*)hp = H.u;
    *(uint2*)lp = L.u;
}

__device__ __forceinline__ u32 smem_u32(const void* p) {
    u32 a;
    asm("{ .reg .u64 t; cvta.to.shared.u64 t, %1; cvt.u32.u64 %0, t; }"
        : "=r"(a) : "l"(p));
    return a;
}
__device__ __forceinline__ void cpasync16(u32 dst, const void* src) {
    asm volatile("cp.async.cg.shared.global [%0], [%1], 16;"
                 :: "r"(dst), "l"(src) : "memory");
}
#define CP_COMMIT() asm volatile("cp.async.commit_group;" ::: "memory")

// packed f32x2 helpers
typedef unsigned long long uu64;
__device__ __forceinline__ uu64 pack2(float x, float y) {
    uu64 r; asm("mov.b64 %0, {%1, %2};" : "=l"(r) : "f"(x), "f"(y)); return r;
}
__device__ __forceinline__ void fma2(uu64& d, uu64 a, uu64 b) {
    asm("fma.rn.f32x2 %0, %1, %2, %0;" : "+l"(d) : "l"(a), "l"(b));
}
__device__ __forceinline__ float2 unpack2(uu64 v) {
    float2 f; asm("mov.b64 {%0, %1}, %2;" : "=f"(f.x), "=f"(f.y) : "l"(v)); return f;
}

// ---------------------------------------------------------------------------
// split conversion kernels
// ---------------------------------------------------------------------------
__global__ void __launch_bounds__(256)
splitF32(const float* __restrict__ x, __nv_bfloat16* __restrict__ hi,
         __nv_bfloat16* __restrict__ lo)
{
    const int i = blockIdx.x * 256 + threadIdx.x;   // float4 index
    float4 v = ((const float4*)x)[i];
    split_store4(hi + 4 * (long)i, lo + 4 * (long)i, v);
}

// WkT[h][n][k] = split(Wk[h*64+k][n]); flat t = h*32768 + n*64 + k
__global__ void __launch_bounds__(256)
splitWkT(const float* __restrict__ Wk, __nv_bfloat16* __restrict__ hi,
         __nv_bfloat16* __restrict__ lo)
{
    const int t = blockIdx.x * 256 + threadIdx.x;
    const int k = t & 63, n = (t >> 6) & 511, h = t >> 15;
    float v = Wk[(h * 64 + k) * DIM + n];
    __nv_bfloat16 a, b;
    split1(v, a, b);
    hi[t] = a; lo[t] = b;
}

// ---------------------------------------------------------------------------
// wmma bf16 GEMM, hi/lo split (3 products), single-buffered BK=32 (R13 winner).
//   C[m, z*cz + bn + j] = (sum_k A[m,k]*B[n,k] + bias) * alpha
// Block: 256 thr = 8 warps (4m x 2n); tile M=128, N=BN.
// SMEM rows padded to ld=40 bf16 (80B, 16B multiple).
// ---------------------------------------------------------------------------
template <int BN, bool SPLIT_OUT>
__global__ void __launch_bounds__(256)
wmmaGemm(const __nv_bfloat16* __restrict__ aHi, const __nv_bfloat16* __restrict__ aLo,
         int lda, int az,
         const __nv_bfloat16* __restrict__ bHi, const __nv_bfloat16* __restrict__ bLo,
         int ldb, int bz,
         const float* __restrict__ bias, int biasz,
         float* __restrict__ cF,
         __nv_bfloat16* __restrict__ cHi, __nv_bfloat16* __restrict__ cLo,
         int ldc, long cz,
         int K, float alpha)
{
    extern __shared__ __align__(16) char smem[];
    constexpr int LDS   = 40;                         // padded bf16 ld
    constexpr int A_SZ  = 128 * LDS * 2;              // bytes per A matrix
    constexpr int B_SZ  = BN * LDS * 2;
    constexpr int OFF_BIAS = 0;
    constexpr int OFF_A_HI = 1024;
    constexpr int OFF_A_LO = OFF_A_HI + A_SZ;
    constexpr int OFF_B_HI = OFF_A_LO + A_SZ;
    constexpr int OFF_B_LO = OFF_B_HI + B_SZ;
    constexpr int OFF_C    = 1024;                    // overlays A/B post-mainloop
    constexpr int WN    = BN / 2;                     // warp tile n
    constexpr int NFRAG = WN / 16;

    const int tid  = threadIdx.x;
    const int wid  = tid >> 5;
    const int bm   = blockIdx.y * 128;
    const int bn   = blockIdx.x * BN;
    const int z    = blockIdx.z;
    const int wm   = (wid >> 1) * 32;                 // warp m offset in tile
    const int wn   = (wid & 1) * WN;                  // warp n offset in tile

    aHi += (long)z * az;  aLo += (long)z * az;
    bHi += (long)z * bz;  bLo += (long)z * bz;

    if (tid < BN) {
        float bvv = bias ? bias[(long)z * biasz + bn + tid] : 0.f;
        *(float*)(smem + OFF_BIAS + tid * 4) = bvv;
    }

    __nv_bfloat16* AsHi = (__nv_bfloat16*)(smem + OFF_A_HI);
    __nv_bfloat16* AsLo = (__nv_bfloat16*)(smem + OFF_A_LO);
    __nv_bfloat16* BsHi = (__nv_bfloat16*)(smem + OFF_B_HI);
    __nv_bfloat16* BsLo = (__nv_bfloat16*)(smem + OFF_B_LO);

    wmma::fragment<wmma::accumulator, 16, 16, 16, float> acc[2][NFRAG];
#pragma unroll
    for (int mi = 0; mi < 2; mi++)
#pragma unroll
        for (int ni = 0; ni < NFRAG; ni++) wmma::fill_fragment(acc[mi][ni], 0.f);

    const int nChunks = K >> 5;                       // BK = 32
    for (int kc = 0; kc < nChunks; kc++) {
        const int kOff = kc * 32;
        // A: 128 rows x 32 bf16 -> 4 uint4/row, 512 uint4, 2 per thread
#pragma unroll
        for (int i = 0; i < 2; i++) {
            int t = tid + 256 * i;
            int r = t >> 2, cq = t & 3;
            *(uint4*)(AsHi + r * LDS + cq * 8) =
                *(const uint4*)(aHi + (long)(bm + r) * lda + kOff + cq * 8);
            *(uint4*)(AsLo + r * LDS + cq * 8) =
                *(const uint4*)(aLo + (long)(bm + r) * lda + kOff + cq * 8);
        }
        // B: BN rows x 32 bf16
#pragma unroll
        for (int i = 0; i < BN / 64; i++) {
            int t = tid + 256 * i;
            int r = t >> 2, cq = t & 3;
            *(uint4*)(BsHi + r * LDS + cq * 8) =
                *(const uint4*)(bHi + (long)(bn + r) * ldb + kOff + cq * 8);
            *(uint4*)(BsLo + r * LDS + cq * 8) =
                *(const uint4*)(bLo + (long)(bn + r) * ldb + kOff + cq * 8);
        }
        __syncthreads();

#pragma unroll
        for (int kf = 0; kf < 32; kf += 16) {
            wmma::fragment<wmma::matrix_a, 16, 16, 16, __nv_bfloat16, wmma::row_major> aH[2], aL[2];
#pragma unroll
            for (int mi = 0; mi < 2; mi++) {
                wmma::load_matrix_sync(aH[mi], AsHi + (wm + mi * 16) * LDS + kf, LDS);
                wmma::load_matrix_sync(aL[mi], AsLo + (wm + mi * 16) * LDS + kf, LDS);
            }
#pragma unroll
            for (int ni = 0; ni < NFRAG; ni++) {
                wmma::fragment<wmma::matrix_b, 16, 16, 16, __nv_bfloat16, wmma::col_major> bH, bL;
                wmma::load_matrix_sync(bH, BsHi + (wn + ni * 16) * LDS + kf, LDS);
                wmma::load_matrix_sync(bL, BsLo + (wn + ni * 16) * LDS + kf, LDS);
#pragma unroll
                for (int mi = 0; mi < 2; mi++) {
                    wmma::mma_sync(acc[mi][ni], aH[mi], bH, acc[mi][ni]);
                    wmma::mma_sync(acc[mi][ni], aH[mi], bL, acc[mi][ni]);
                    wmma::mma_sync(acc[mi][ni], aL[mi], bH, acc[mi][ni]);
                }
            }
        }
        __syncthreads();
    }

    // ---- epilogue: frags -> smem C overlay -> bias/alpha/(split) global ----
    float* Cs = (float*)(smem + OFF_C);
#pragma unroll
    for (int mi = 0; mi < 2; mi++)
#pragma unroll
        for (int ni = 0; ni < NFRAG; ni++)
            wmma::store_matrix_sync(Cs + (wm + mi * 16) * BN + wn + ni * 16,
                                    acc[mi][ni], BN, wmma::mem_row_major);
    __syncthreads();

    const float* bs = (const float*)(smem + OFF_BIAS);
    constexpr int NV = 128 * BN / 4 / 256;            // float4s per thread
#pragma unroll
    for (int i = 0; i < NV; i++) {
        int t = tid + 256 * i;
        int r = t / (BN / 4);
        int c4 = t % (BN / 4);
        float4 v = *(float4*)(Cs + r * BN + c4 * 4);
        v.x = (v.x + bs[c4 * 4 + 0]) * alpha;
        v.y = (v.y + bs[c4 * 4 + 1]) * alpha;
        v.z = (v.z + bs[c4 * 4 + 2]) * alpha;
        v.w = (v.w + bs[c4 * 4 + 3]) * alpha;
        const long off = (long)(bm + r) * ldc + (long)z * cz + bn + c4 * 4;
        if (SPLIT_OUT) split_store4(cHi + off, cLo + off, v);
        else           *(float4*)(cF + off) = v;
    }
}

// ---------------------------------------------------------------------------
// Attention core (SIMT fp32, packed f32x2): one CTA per batch, 256 threads.
// ctx (35x512 fp32 = 70KB) staged ONCE via cp.async; 4 HEADS PER WARP so each
// staged row is read only 2x (phase B) + 2x (phase C) instead of 4x+4x.
//  Phase B: warp (hq, jg) -> heads 4hq..4hq+3, j-group of 9   (8 warps)
//  Softmax: warp = head
//  Phase C: warp (hq, dq) -> heads 4hq..4hq+3, 128-dim quarter
// w written as SPLIT bf16 for the tensor G4.
// ---------------------------------------------------------------------------
__global__ void __launch_bounds__(256)
attn_core(const float* __restrict__ qt, const float* __restrict__ cc,
          const float* __restrict__ hv, const float* __restrict__ ev,
          const float* __restrict__ sv,
          __nv_bfloat16* __restrict__ whi, __nv_bfloat16* __restrict__ wlo)
{
    extern __shared__ __align__(16) float smbuf[];
    float* ctx   = smbuf;                    // [35][512]
    float* sc    = smbuf + KCTX * DIM;       // [8][35]
    float* attnw = sc + HEADS * KCTX;        // [8][35]

    const int n    = blockIdx.x;
    const int tid  = threadIdx.x;
    const int lane = tid & 31;
    const int warp = tid >> 5;
    const u32 sb   = smem_u32(smbuf);

    // ---- stage ctx via cp.async: c rows 0..31 (64KB) + h/e/s rows ----------
    {
        const float* cbase = cc + (long)n * 32 * DIM;
#pragma unroll
        for (int i = 0; i < 16; i++) {
            const int t = tid + 256 * i;               // 0..4095 (16B units)
            cpasync16(sb + t * 16, cbase + t * 4);
        }
        for (int i = tid; i < 384; i += 256) {         // 3 rows x 128 x 16B
            const int r = i >> 7, v = i & 127;
            const float* src = (r == 0) ? hv : (r == 1) ? ev : sv;
            cpasync16(sb + (32 + r) * DIM * 4 + v * 16, src + (long)n * DIM + v * 4);
        }
        CP_COMMIT();
        asm volatile("cp.async.wait_group 0;" ::: "memory");
    }
    __syncthreads();

    const int hq    = warp >> 2;             // 0,1
    const int hbase = hq * 4;

    // ---- Phase B: scores (each warp: 4 heads x 9 ctx rows) -----------------
    {
        uu64 q2[4][8];
#pragma unroll
        for (int hd = 0; hd < 4; hd++) {
            const float4* qp = (const float4*)(qt + (long)n * (HEADS * DIM) +
                                               (hbase + hd) * DIM);
#pragma unroll
            for (int i = 0; i < 4; i++) {
                float4 r = qp[lane + 32 * i];
                q2[hd][2 * i]     = pack2(r.x, r.y);
                q2[hd][2 * i + 1] = pack2(r.z, r.w);
            }
        }
        const int jg = warp & 3;
        const int jb = jg * 9;
        const int je = (jb + 9 < KCTX) ? jb + 9 : KCTX;
        for (int j = jb; j < je; j++) {
            const ulonglong2* xp = (const ulonglong2*)(ctx + j * DIM);
            uu64 p[4] = {0ull, 0ull, 0ull, 0ull};
#pragma unroll
            for (int i = 0; i < 4; i++) {
                ulonglong2 x = xp[lane + 32 * i];
#pragma unroll
                for (int hd = 0; hd < 4; hd++) {
                    fma2(p[hd], q2[hd][2 * i],     x.x);
                    fma2(p[hd], q2[hd][2 * i + 1], x.y);
                }
            }
#pragma unroll
            for (int hd = 0; hd < 4; hd++) {
                float2 f = unpack2(p[hd]);
                float sv_ = f.x + f.y;
#pragma unroll
                for (int o = 16; o; o >>= 1)
                    sv_ += __shfl_xor_sync(0xffffffffu, sv_, o);
                if (lane == 0) sc[(hbase + hd) * KCTX + j] = sv_;
            }
        }
    }
    __syncthreads();

    // ---- Softmax (warp = head) ----------------------------------------------
    {
        const int hh = warp;
        float s1 = sc[hh * KCTX + lane];
        float s2 = (lane < 3) ? sc[hh * KCTX + 32 + lane] : -3.0e38f;
        float m = fmaxf(s1, s2);
#pragma unroll
        for (int o = 16; o; o >>= 1)
            m = fmaxf(m, __shfl_xor_sync(0xffffffffu, m, o));
        float e1 = expf(s1 - m);
        float e2 = (lane < 3) ? expf(s2 - m) : 0.f;
        float sum = e1 + e2;
#pragma unroll
        for (int o = 16; o; o >>= 1)
            sum += __shfl_xor_sync(0xffffffffu, sum, o);
        float inv = 1.f / sum;
        attnw[hh * KCTX + lane] = e1 * inv;
        if (lane < 3) attnw[hh * KCTX + 32 + lane] = e2 * inv;
    }
    __syncthreads();

    // ---- Phase C: w = attn @ ctx (each warp: 4 heads x 128-dim quarter) ----
    {
        const int dq    = warp & 3;
        const int dbase = dq * 128;            // floats
        uu64 acc2[4][2];
#pragma unroll
        for (int hd = 0; hd < 4; hd++) { acc2[hd][0] = 0ull; acc2[hd][1] = 0ull; }

        for (int j = 0; j < KCTX; j++) {
            ulonglong2 x = ((const ulonglong2*)(ctx + j * DIM + dbase))[lane];
#pragma unroll
            for (int hd = 0; hd < 4; hd++) {
                float aw = attnw[(hbase + hd) * KCTX + j];
                uu64 ad = pack2(aw, aw);
                fma2(acc2[hd][0], ad, x.x);
                fma2(acc2[hd][1], ad, x.y);
            }
        }
#pragma unroll
        for (int hd = 0; hd < 4; hd++) {
            const long off = (long)n * (HEADS * DIM) + (hbase + hd) * DIM +
                             dbase + 4 * lane;
            float2 a = unpack2(acc2[hd][0]);
            float2 b = unpack2(acc2[hd][1]);
            split_store4(whi + off, wlo + off, make_float4(a.x, a.y, b.x, b.y));
        }
    }
}

// ---------------------------------------------------------------------------
// relu + LayerNorm (ddof=1, eps added to STD). One warp per row.
// ---------------------------------------------------------------------------
__global__ void __launch_bounds__(256)
relu_ln(const float* __restrict__ y, const float* __restrict__ ln_a,
        const float* __restrict__ ln_b, float* __restrict__ out)
{
    const int lane = threadIdx.x & 31;
    const int warp = threadIdx.x >> 5;
    const int row  = blockIdx.x * 8 + warp;

    const float4* xr = (const float4*)(y + (long)row * DIM);
    float4 v[4];
    float sum = 0.f;
#pragma unroll
    for (int i = 0; i < 4; i++) {
        float4 x = xr[lane + 32 * i];
        x.x = fmaxf(x.x, 0.f); x.y = fmaxf(x.y, 0.f);
        x.z = fmaxf(x.z, 0.f); x.w = fmaxf(x.w, 0.f);
        v[i] = x;
        sum += x.x + x.y + x.z + x.w;
    }
#pragma unroll
    for (int o = 16; o; o >>= 1) sum += __shfl_xor_sync(0xffffffffu, sum, o);
    const float mean = sum * (1.f / (float)DIM);

    float ssq = 0.f;
#pragma unroll
    for (int i = 0; i < 4; i++) {
        float dx;
        dx = v[i].x - mean; ssq = fmaf(dx, dx, ssq);
        dx = v[i].y - mean; ssq = fmaf(dx, dx, ssq);
        dx = v[i].z - mean; ssq = fmaf(dx, dx, ssq);
        dx = v[i].w - mean; ssq = fmaf(dx, dx, ssq);
    }
#pragma unroll
    for (int o = 16; o; o >>= 1) ssq += __shfl_xor_sync(0xffffffffu, ssq, o);
    const float stddev = sqrtf(ssq * (1.f / (float)(DIM - 1)));
    const float inv = 1.f / (stddev + 1e-6f);

    float4* orow = (float4*)(out + (long)row * DIM);
    const float4* a4 = (const float4*)ln_a;
    const float4* b4 = (const float4*)ln_b;
#pragma unroll
    for (int i = 0; i < 4; i++) {
        const int idx = lane + 32 * i;
        float4 a = a4[idx], b = b4[idx], o4;
        o4.x = fmaf(a.x * inv, v[i].x - mean, b.x);
        o4.y = fmaf(a.y * inv, v[i].y - mean, b.y);
        o4.z = fmaf(a.z * inv, v[i].z - mean, b.z);
        o4.w = fmaf(a.w * inv, v[i].w - mean, b.w);
        orow[idx] = o4;
    }
}

// ---------------------------------------------------------------------------
extern "C" void kernel_launch(void* const* d_in, const int* in_sizes, int n_in,
                              void* d_out, int out_size)
{
    const float* c   = (const float*)d_in[0];
    const float* h   = (const float*)d_in[1];
    const float* e   = (const float*)d_in[2];
    const float* s   = (const float*)d_in[3];
    const float* Wq  = (const float*)d_in[4];
    const float* bq  = (const float*)d_in[5];
    const float* Wk  = (const float*)d_in[6];
    /* bk = d_in[7] unused: constant across softmax axis, drops exactly */
    const float* Wv  = (const float*)d_in[8];
    const float* bv  = (const float*)d_in[9];
    const float* Wo  = (const float*)d_in[10];
    const float* bo  = (const float*)d_in[11];
    const float* la  = (const float*)d_in[12];
    const float* lb  = (const float*)d_in[13];
    float* out = (float*)d_out;

    void *p;
    __nv_bfloat16 *hHi, *hLo, *wqHi, *wqLo, *wkHi, *wkLo, *wvHi, *wvLo, *woHi, *woLo;
    __nv_bfloat16 *qpHi, *qpLo, *wHi, *wLo, *oHi, *oLo;
    float *qt, *y;
    cudaGetSymbolAddress(&p, g_h_hi);   hHi  = (__nv_bfloat16*)p;
    cudaGetSymbolAddress(&p, g_h_lo);   hLo  = (__nv_bfloat16*)p;
    cudaGetSymbolAddress(&p, g_wq_hi);  wqHi = (__nv_bfloat16*)p;
    cudaGetSymbolAddress(&p, g_wq_lo);  wqLo = (__nv_bfloat16*)p;
    cudaGetSymbolAddress(&p, g_wkT_hi); wkHi = (__nv_bfloat16*)p;
    cudaGetSymbolAddress(&p, g_wkT_lo); wkLo = (__nv_bfloat16*)p;
    cudaGetSymbolAddress(&p, g_wv_hi);  wvHi = (__nv_bfloat16*)p;
    cudaGetSymbolAddress(&p, g_wv_lo);  wvLo = (__nv_bfloat16*)p;
    cudaGetSymbolAddress(&p, g_wo_hi);  woHi = (__nv_bfloat16*)p;
    cudaGetSymbolAddress(&p, g_wo_lo);  woLo = (__nv_bfloat16*)p;
    cudaGetSymbolAddress(&p, g_qp_hi);  qpHi = (__nv_bfloat16*)p;
    cudaGetSymbolAddress(&p, g_qp_lo);  qpLo = (__nv_bfloat16*)p;
    cudaGetSymbolAddress(&p, g_qt);     qt   = (float*)p;
    cudaGetSymbolAddress(&p, g_w_hi);   wHi  = (__nv_bfloat16*)p;
    cudaGetSymbolAddress(&p, g_w_lo);   wLo  = (__nv_bfloat16*)p;
    cudaGetSymbolAddress(&p, g_o_hi);   oHi  = (__nv_bfloat16*)p;
    cudaGetSymbolAddress(&p, g_o_lo);   oLo  = (__nv_bfloat16*)p;
    cudaGetSymbolAddress(&p, g_y);      y    = (float*)p;

    // smem sizes: 1024 + max(A/B tiles, C overlay)
    const int SM128 = 1024 + ((2 * 128 * 40 * 2 + 2 * 128 * 40 * 2) > (128 * 128 * 4)
                              ? (2 * 128 * 40 * 2 + 2 * 128 * 40 * 2) : (128 * 128 * 4));
    const int SM64  = 1024 + ((2 * 128 * 40 * 2 + 2 * 64 * 40 * 2) > (128 * 64 * 4)
                              ? (2 * 128 * 40 * 2 + 2 * 64 * 40 * 2) : (128 * 64 * 4));
    const int ATTN_SMEM = (KCTX * DIM + 2 * HEADS * KCTX) * (int)sizeof(float);

    cudaFuncSetAttribute(wmmaGemm<128, true>,
                         cudaFuncAttributeMaxDynamicSharedMemorySize, SM128);
    cudaFuncSetAttribute(wmmaGemm<128, false>,
                         cudaFuncAttributeMaxDynamicSharedMemorySize, SM128);
    cudaFuncSetAttribute(wmmaGemm<64, true>,
                         cudaFuncAttributeMaxDynamicSharedMemorySize, SM64);
    cudaFuncSetAttribute(attn_core,
                         cudaFuncAttributeMaxDynamicSharedMemorySize, ATTN_SMEM);

    // 0) conversions — ordered so launch #6 (ncu -s 5 -c 1) is the G1 GEMM
    splitWkT<<<DIM * DIM / 256, 256>>>(Wk, wkHi, wkLo);
    splitF32<<<DIM * DIM / 4 / 256, 256>>>(Wq, wqHi, wqLo);
    splitF32<<<DIM * DIM / 4 / 256, 256>>>(Wv, wvHi, wvLo);
    splitF32<<<DIM * DIM / 4 / 256, 256>>>(Wo, woHi, woLo);
    splitF32<<<NB * DIM / 4 / 256, 256>>>(h, hHi, hLo);

    // 1) qp = (h @ Wq^T + bq)*0.125 -> split bf16        [launch #6: profiled]
    wmmaGemm<128, true><<<dim3(4, 64, 1), 256, SM128>>>(
        hHi, hLo, DIM, 0, wqHi, wqLo, DIM, 0, bq, 0,
        (float*)0, qpHi, qpLo, DIM, 0, DIM, 0.125f);

    // 2) qt[n, h*512+d] = qp_h @ WkT_h^T  (z = head, K = 64) -> fp32
    wmmaGemm<128, false><<<dim3(4, 64, 8), 256, SM128>>>(
        qpHi, qpLo, DIM, 64, wkHi, wkLo, 64, 512 * 64, (const float*)0, 0,
        qt, (__nv_bfloat16*)0, (__nv_bfloat16*)0, HEADS * DIM, DIM, 64, 1.0f);

    // 3) attention core -> w split bf16
    attn_core<<<NB, 256, ATTN_SMEM>>>(qt, c, h, e, s, wHi, wLo);

    // 4) o[:, h*64..] = w_h @ Wv_h^T + bv_h (z = head) -> split bf16
    wmmaGemm<64, true><<<dim3(1, 64, 8), 256, SM64>>>(
        wHi, wLo, HEADS * DIM, DIM, wvHi, wvLo, DIM, 64 * DIM, bv, 64,
        (float*)0, oHi, oLo, DIM, 64, DIM, 1.0f);

    // 5) y = o @ Wo^T + bo -> fp32
    wmmaGemm<128, false><<<dim3(4, 64, 1), 256, SM128>>>(
        oHi, oLo, DIM, 0, woHi, woLo, DIM, 0, bo, 0,
        y, (__nv_bfloat16*)0, (__nv_bfloat16*)0, DIM, 0, DIM, 1.0f);

    // 6) out = LN(relu(y))
    relu_ln<<<NB / 8, 256>>>(y, la, lb, out);
}